// round 8
// baseline (speedup 1.0000x reference)
#include <cuda_runtime.h>
#include <math.h>

#define MM 2000
#define NB 4096
#define CAND 4096
#define EDGE_MAX 4096
#define T_STATIC 0.99925f
#define TB 32
#define NT ((MM + TB - 1) / TB)        // 63 tiles per dim
#define NTILES (NT * (NT + 1) / 2)     // 2016 upper-triangle tiles

// ---------------- device scratch (zero-initialized at module load) ----------------
__device__ int                g_candCount;
__device__ int                g_cnt;
__device__ int                g_nValid;
__device__ int                g_edgeCount;
__device__ unsigned           g_done1, g_done2;
__device__ unsigned long long g_cand[CAND];
__device__ unsigned long long g_top[CAND];     // counting-sort output (desc order)
__device__ float4             g_boxes[MM];
__device__ int                g_keep0[MM];
__device__ unsigned int       g_edges[EDGE_MAX];

// ---------------- k_main: streaming speculative compact + last-block validation --
__global__ __launch_bounds__(1024) void k_main(const float4* __restrict__ s4, int n4,
                                               const float2* __restrict__ score, int n) {
    int nthr = gridDim.x * blockDim.x;
    int tid  = blockIdx.x * blockDim.x + threadIdx.x;
    for (int i = tid; i < n4; i += 4 * nthr) {
        int i1 = i + nthr, i2 = i + 2 * nthr, i3 = i + 3 * nthr;
        bool b1 = i1 < n4, b2 = i2 < n4, b3 = i3 < n4;
        float4 a0 = s4[i];
        float4 a1, a2, a3;
        if (b1) a1 = s4[i1];
        if (b2) a2 = s4[i2];
        if (b3) a3 = s4[i3];
        #define EMIT(v, idx)                                                        \
            if ((v) > T_STATIC) {                                                   \
                int pos = atomicAdd(&g_candCount, 1);                               \
                if (pos < CAND)                                                     \
                    g_cand[pos] = ((unsigned long long)__float_as_uint(v) << 32) |  \
                                  (unsigned long long)(0xFFFFFFFFu - (idx));        \
            }
        EMIT(a0.y, 2u * (unsigned)i)
        EMIT(a0.w, 2u * (unsigned)i + 1u)
        if (b1) { EMIT(a1.y, 2u * (unsigned)i1) EMIT(a1.w, 2u * (unsigned)i1 + 1u) }
        if (b2) { EMIT(a2.y, 2u * (unsigned)i2) EMIT(a2.w, 2u * (unsigned)i2 + 1u) }
        if (b3) { EMIT(a3.y, 2u * (unsigned)i3) EMIT(a3.w, 2u * (unsigned)i3 + 1u) }
        #undef EMIT
    }

    // ---- last-finishing block validates (exact fallback only if speculation failed)
    __shared__ int s_last;
    __syncthreads();
    if (threadIdx.x == 0) {
        __threadfence();
        unsigned d = atomicAdd(&g_done1, 1u);
        s_last = (d == gridDim.x - 1) ? 1 : 0;
    }
    __syncthreads();
    if (!s_last) return;

    int t = threadIdx.x;
    __shared__ int s_fb;
    if (t == 0) {
        g_done1 = 0;
        int c = g_candCount;
        s_fb = (c < MM || c > CAND);
        if (!s_fb) { g_cnt = c; g_nValid = MM; g_edgeCount = 0; }
    }
    __syncthreads();
    if (!s_fb) return;

    // pathological fallback: exact histogram selection by this one block
    __shared__ unsigned sh[NB];
    __shared__ unsigned s_cut;
    __shared__ int s_cnt2;
    for (int i = t; i < NB; i += 1024) sh[i] = 0u;
    __syncthreads();
    for (int i = t; i < n; i += 1024) {
        float v = score[i].y;
        if (v > 0.5f) {
            unsigned u = __float_as_uint(v);
            unsigned b = (u - 0x3F000000u) >> 11;
            if (b > NB - 1u) b = NB - 1u;
            atomicAdd(&sh[b], 1u);
        }
    }
    __syncthreads();
    if (t == 0) {
        unsigned run = 0; unsigned cut = 0;
        for (int b = NB - 1; b >= 0; b--) {
            run += sh[b];
            if (run >= (unsigned)MM) { cut = (unsigned)b; break; }
        }
        s_cut = cut;
        s_cnt2 = 0;
    }
    __syncthreads();
    unsigned cut = s_cut;
    for (int i = t; i < n; i += 1024) {
        float v = score[i].y;
        if (v > 0.5f) {
            unsigned u = __float_as_uint(v);
            unsigned b = (u - 0x3F000000u) >> 11;
            if (b > NB - 1u) b = NB - 1u;
            if (b >= cut) {
                int pos = atomicAdd(&s_cnt2, 1);
                if (pos < CAND)
                    g_cand[pos] = ((unsigned long long)u << 32) |
                                  (unsigned long long)(0xFFFFFFFFu - (unsigned)i);
            }
        }
    }
    __syncthreads();
    if (t == 0) {
        int c2 = s_cnt2; if (c2 > CAND) c2 = CAND;
        g_cnt = c2;
        g_nValid = (c2 < MM) ? c2 : MM;
        g_edgeCount = 0;
    }
}

// ---------------- k_rank2: counting-sort rank (O(n)) + fused decode --------------
// Single block. Monotone integer bucket map -> hist -> suffix scan -> scatter ->
// per-bucket insertion sort (avg <1 key/bucket) -> decode top-MM boxes.
__global__ __launch_bounds__(1024) void k_rank2(const float4* __restrict__ anchors,
                                                const float4* __restrict__ deltas) {
    __shared__ unsigned bCnt[NB];    // 16 KB
    __shared__ unsigned bStart[NB];  // 16 KB (mutates to end during scatter)
    __shared__ unsigned wsum[32];
    __shared__ unsigned s_umin, s_umax;
    int t = threadIdx.x;
    int cnt = g_cnt; if (cnt > CAND) cnt = CAND;
    if (cnt <= 0) return;            // nValid=0 handles output

    if (t == 0) { s_umin = 0xFFFFFFFFu; s_umax = 0u; }
    for (int i = t; i < NB; i += 1024) bCnt[i] = 0u;
    __syncthreads();

    // min/max of score bits
    unsigned lmin = 0xFFFFFFFFu, lmax = 0u;
    for (int i = t; i < cnt; i += 1024) {
        unsigned u = (unsigned)(g_cand[i] >> 32);
        lmin = min(lmin, u); lmax = max(lmax, u);
    }
    atomicMin(&s_umin, lmin);
    atomicMax(&s_umax, lmax);
    __syncthreads();
    unsigned umin = s_umin;
    unsigned long long range = (unsigned long long)(s_umax - umin) + 1ull;

    // histogram
    for (int i = t; i < cnt; i += 1024) {
        unsigned u = (unsigned)(g_cand[i] >> 32);
        unsigned b = (unsigned)((((unsigned long long)(u - umin)) << 12) / range);
        atomicAdd(&bCnt[b], 1u);
    }
    __syncthreads();

    // suffix scan: bStart[b] = #keys in buckets > b (thread t owns chunk 1023-t)
    {
        int chunk = 1023 - t;
        unsigned orig = bCnt[chunk*4+0] + bCnt[chunk*4+1] + bCnt[chunk*4+2] + bCnt[chunk*4+3];
        unsigned v = orig;
        int lane = t & 31, wid = t >> 5;
        #pragma unroll
        for (int d = 1; d < 32; d <<= 1) {
            unsigned nv = __shfl_up_sync(0xffffffffu, v, d);
            if (lane >= d) v += nv;
        }
        if (lane == 31) wsum[wid] = v;
        __syncthreads();
        if (wid == 0) {
            unsigned w = wsum[lane];
            #pragma unroll
            for (int d = 1; d < 32; d <<= 1) {
                unsigned nw = __shfl_up_sync(0xffffffffu, w, d);
                if (lane >= d) w += nw;
            }
            wsum[lane] = w;
        }
        __syncthreads();
        unsigned incl = v + (wid ? wsum[wid - 1] : 0u);
        unsigned run = incl - orig;   // keys strictly above this chunk
        #pragma unroll
        for (int j = 3; j >= 0; j--) {
            int b = chunk * 4 + j;
            bStart[b] = run;
            run += bCnt[b];
        }
    }
    __syncthreads();

    // scatter (bStart becomes bucket end)
    for (int i = t; i < cnt; i += 1024) {
        unsigned long long k = g_cand[i];
        unsigned u = (unsigned)(k >> 32);
        unsigned b = (unsigned)((((unsigned long long)(u - umin)) << 12) / range);
        unsigned slot = atomicAdd(&bStart[b], 1u);
        g_top[slot] = k;
    }
    __syncthreads();

    // per-bucket descending insertion sort (len avg <1; exact tie-order via full key)
    for (int b = t; b < NB; b += 1024) {
        unsigned len = bCnt[b];
        if (len >= 2) {
            unsigned start = bStart[b] - len;
            for (unsigned a = 1; a < len; a++) {
                unsigned long long key = g_top[start + a];
                int c = (int)a - 1;
                while (c >= 0 && g_top[start + c] < key) {
                    g_top[start + c + 1] = g_top[start + c];
                    c--;
                }
                g_top[start + c + 1] = key;
            }
        }
    }
    __syncthreads();

    // decode top-MM boxes (2 independent gathers per thread)
    #pragma unroll
    for (int r = 0; r < 2; r++) {
        int m = t + r * 1024;
        if (m >= MM) break;
        if (m < cnt) {
            unsigned long long key = g_top[m];
            unsigned idx = 0xFFFFFFFFu - (unsigned)(key & 0xFFFFFFFFull);
            float4 a = __ldg(anchors + idx);
            float4 d = __ldg(deltas + idx);
            float w  = a.z - a.x;
            float h  = a.w - a.y;
            float cx = a.x + 0.5f * w;
            float cy = a.y + 0.5f * h;
            float ncx = cx + d.x * w;
            float ncy = cy + d.y * h;
            float nw  = w * expf(d.z);
            float nh  = h * expf(d.w);
            float x1 = ncx - 0.5f * nw, y1 = ncy - 0.5f * nh;
            float x2 = ncx + 0.5f * nw, y2 = ncy + 0.5f * nh;
            x1 = fminf(fmaxf(x1, 0.f), 1024.f);
            y1 = fminf(fmaxf(y1, 0.f), 1024.f);
            x2 = fminf(fmaxf(x2, 0.f), 1024.f);
            y2 = fminf(fmaxf(y2, 0.f), 1024.f);
            bool big = ((x2 - x1) >= 1.0f) && ((y2 - y1) >= 1.0f);
            g_boxes[m] = make_float4(x1, y1, x2, y2);
            g_keep0[m] = big ? 1 : 0;
        } else {
            g_keep0[m] = 0;
        }
    }
    if (t == 0) g_candCount = 0;   // reset for next replay
}

// ---------------- k_pairs: one block per 32x32 upper-triangle tile, one pair per
//                  thread; last-finishing block runs the NMS finalize epilogue ----
__global__ __launch_bounds__(1024) void k_pairs(float* __restrict__ out) {
    int t = threadIdx.x; // 1024
    int nV = g_nValid;

    {
        int tile = blockIdx.x;
        int bx = 0, rem = tile;
        while (rem >= NT - bx) { rem -= NT - bx; bx++; }
        int by = bx + rem;
        int i = bx * TB + (t >> 5);
        int j = by * TB + (t & 31);
        if (i < nV && j < nV && j > i && g_keep0[i] && g_keep0[j]) {
            float4 A = g_boxes[i];   // warp-uniform -> L1 broadcast
            float4 B = g_boxes[j];   // coalesced across lanes
            float ai = (A.z - A.x) * (A.w - A.y);
            float aj = (B.z - B.x) * (B.w - B.y);
            float ltx = fmaxf(A.x, B.x), lty = fmaxf(A.y, B.y);
            float rbx = fminf(A.z, B.z), rby = fminf(A.w, B.w);
            float iw = fmaxf(rbx - ltx, 0.f), ih = fmaxf(rby - lty, 0.f);
            float inter = iw * ih;
            float iou = inter / (ai + aj - inter + 1e-9f);
            if (iou > 0.7f) {
                int pos = atomicAdd(&g_edgeCount, 1);
                if (pos < EDGE_MAX) g_edges[pos] = ((unsigned)i << 16) | (unsigned)j;
            }
        }
    }

    // ---- last-finishing block runs finalize ----
    __shared__ int s_last;
    __syncthreads();
    if (t == 0) {
        __threadfence();
        unsigned d = atomicAdd(&g_done2, 1u);
        s_last = (d == gridDim.x - 1) ? 1 : 0;
    }
    __syncthreads();
    if (!s_last) return;

    __shared__ unsigned char dead[MM];
    __shared__ unsigned se[EDGE_MAX]; // 16 KB
    for (int m = t; m < MM; m += 1024) dead[m] = (m < nV && g_keep0[m]) ? 0 : 1;
    int ec = g_edgeCount; if (ec > EDGE_MAX) ec = EDGE_MAX;
    for (int i = t; i < EDGE_MAX; i += 1024) se[i] = (i < ec) ? g_edges[i] : 0xFFFFFFFFu;
    __syncthreads();

    if (ec > 256) {
        for (int k = 2; k <= EDGE_MAX; k <<= 1) {
            for (int j = k >> 1; j > 0; j >>= 1) {
                for (int i = t; i < EDGE_MAX; i += 1024) {
                    int ixj = i ^ j;
                    if (ixj > i) {
                        unsigned a = se[i], b = se[ixj];
                        bool up = ((i & k) == 0);
                        if (up ? (a > b) : (a < b)) { se[i] = b; se[ixj] = a; }
                    }
                }
                __syncthreads();
            }
        }
    } else if (t == 0) {
        for (int a = 1; a < ec; a++) {
            unsigned key = se[a];
            int b = a - 1;
            while (b >= 0 && se[b] > key) { se[b + 1] = se[b]; b--; }
            se[b + 1] = key;
        }
    }
    __syncthreads();

    if (t == 0) {
        for (int e = 0; e < ec; e++) {
            unsigned u = se[e];
            int i = (int)(u >> 16), j = (int)(u & 0xFFFFu);
            if (!dead[i]) dead[j] = 1;
        }
    }
    __syncthreads();

    for (int m = t; m < MM; m += 1024) {
        bool keep = (dead[m] == 0);
        float4 b = g_boxes[m];
        out[m * 4 + 0] = keep ? b.x : 0.f;
        out[m * 4 + 1] = keep ? b.y : 0.f;
        out[m * 4 + 2] = keep ? b.z : 0.f;
        out[m * 4 + 3] = keep ? b.w : 0.f;
        out[MM * 4 + m] = keep ? 1.f : 0.f;
    }
    __syncthreads();
    if (t == 0) {   // reset for next replay
        g_edgeCount = 0;
        g_done2 = 0;
    }
}

// ---------------- launch ----------------
extern "C" void kernel_launch(void* const* d_in, const int* in_sizes, int n_in,
                              void* d_out, int out_size) {
    int si = 0;
    for (int i = 1; i < n_in; i++) if (in_sizes[i] < in_sizes[si]) si = i;
    int others[2], o = 0;
    for (int i = 0; i < n_in && o < 2; i++) if (i != si) others[o++] = i;

    const float4* anchors = (const float4*)d_in[others[0]];
    const float2* score   = (const float2*)d_in[si];
    const float4* deltas  = (const float4*)d_in[others[1]];
    int n  = in_sizes[si] / 2;
    int n4 = in_sizes[si] / 4;

    k_main<<<296, 1024>>>((const float4*)score, n4, score, n);
    k_rank2<<<1, 1024>>>(anchors, deltas);
    k_pairs<<<NTILES, 1024>>>((float*)d_out);
}

// round 9
// speedup vs baseline: 1.0913x; 1.0913x over previous
#include <cuda_runtime.h>
#include <math.h>

#define MM 2000
#define NB 4096
#define CAND 4096
#define EDGE_MAX 4096
#define T_STATIC 0.9994f
#define TB 32
#define NT ((MM + TB - 1) / TB)        // 63 tiles per dim
#define NTILES (NT * (NT + 1) / 2)     // 2016 upper-triangle tiles
#define CH 1024                        // float4 per chunk = 16 KB

// ---------------- device scratch (zero-initialized at module load) ----------------
__device__ int                g_candCount;
__device__ int                g_cnt;
__device__ int                g_nValid;
__device__ int                g_edgeCount;
__device__ unsigned           g_done1, g_done2;
__device__ unsigned long long g_cand[CAND];
__device__ float4             g_boxes[MM];
__device__ int                g_keep0[MM];
__device__ unsigned int       g_edges[EDGE_MAX];

// ---------------- PTX helpers ----------------
__device__ __forceinline__ unsigned smem_u32(const void* p) {
    unsigned a;
    asm("{ .reg .u64 t; cvta.to.shared.u64 t, %1; cvt.u32.u64 %0, t; }" : "=r"(a) : "l"(p));
    return a;
}
__device__ __forceinline__ void mbar_init(unsigned mbar, unsigned count) {
    asm volatile("mbarrier.init.shared.b64 [%0], %1;" :: "r"(mbar), "r"(count) : "memory");
}
__device__ __forceinline__ void mbar_expect_tx(unsigned mbar, unsigned bytes) {
    asm volatile("mbarrier.arrive.expect_tx.shared.b64 _, [%0], %1;" :: "r"(mbar), "r"(bytes) : "memory");
}
__device__ __forceinline__ void bulk_copy(unsigned dst_smem, const void* src, unsigned bytes, unsigned mbar) {
    asm volatile("cp.async.bulk.shared::cta.global.mbarrier::complete_tx::bytes [%0], [%1], %2, [%3];"
                 :: "r"(dst_smem), "l"(src), "r"(bytes), "r"(mbar) : "memory");
}
__device__ __forceinline__ void mbar_wait(unsigned mbar, unsigned parity) {
    unsigned done;
    asm volatile("{ .reg .pred p; mbarrier.try_wait.parity.acquire.cta.shared::cta.b64 p, [%1], %2; selp.b32 %0, 1, 0, p; }"
                 : "=r"(done) : "r"(mbar), "r"(parity) : "memory");
    if (!done) {
        asm volatile("{ .reg .pred P1; WL%=: mbarrier.try_wait.parity.acquire.cta.shared::cta.b64 P1, [%0], %1, 0x989680; @P1 bra.uni WD%=; bra.uni WL%=; WD%=: }"
                     :: "r"(mbar), "r"(parity) : "memory");
    }
}

// ---------------- k_main: bulk-async streaming compact + last-block validation ---
__global__ __launch_bounds__(1024) void k_main(const float4* __restrict__ s4, int n4,
                                               const float2* __restrict__ score, int n) {
    __shared__ float4 stg[2][CH];              // 32 KB double buffer
    __shared__ unsigned long long mbar[2];
    int t = threadIdx.x;

    int nchunks = (n4 + CH - 1) / CH;
    int cpb = (nchunks + gridDim.x - 1) / gridDim.x;
    int c0 = blockIdx.x * cpb;
    int c1 = min(c0 + cpb, nchunks);
    int nc = c1 - c0;

    if (nc > 0) {
        unsigned mb0 = smem_u32(&mbar[0]);
        unsigned mb1 = smem_u32(&mbar[1]);
        unsigned st0 = smem_u32(&stg[0][0]);
        unsigned st1 = smem_u32(&stg[1][0]);
        if (t == 0) { mbar_init(mb0, 1); mbar_init(mb1, 1); }
        __syncthreads();
        if (t == 0) {
            int pre = nc < 2 ? nc : 2;
            for (int k = 0; k < pre; k++) {
                int c = c0 + k;
                unsigned bytes = (unsigned)(min(CH, n4 - c * CH)) * 16u;
                unsigned mb = k ? mb1 : mb0;
                mbar_expect_tx(mb, bytes);
                bulk_copy(k ? st1 : st0, s4 + (long long)c * CH, bytes, mb);
            }
        }
        for (int k = 0; k < nc; k++) {
            int stage = k & 1;
            unsigned parity = (unsigned)((k >> 1) & 1);
            mbar_wait(stage ? smem_u32(&mbar[1]) : smem_u32(&mbar[0]), parity);
            int c = c0 + k;
            int nElem = min(CH, n4 - c * CH);
            if (t < nElem) {
                float4 v = stg[stage][t];
                unsigned row = (unsigned)(c * CH + t);
                #define EMIT(val, idx)                                                      \
                    if ((val) > T_STATIC) {                                                 \
                        int pos = atomicAdd(&g_candCount, 1);                               \
                        if (pos < CAND)                                                     \
                            g_cand[pos] = ((unsigned long long)__float_as_uint(val) << 32) |\
                                          (unsigned long long)(0xFFFFFFFFu - (idx));        \
                    }
                EMIT(v.y, 2u * row)
                EMIT(v.w, 2u * row + 1u)
                #undef EMIT
            }
            __syncthreads();   // all threads done with this stage
            if (t == 0 && k + 2 < nc) {
                int c2 = c0 + k + 2;
                unsigned bytes = (unsigned)(min(CH, n4 - c2 * CH)) * 16u;
                unsigned mb = stage ? smem_u32(&mbar[1]) : smem_u32(&mbar[0]);
                unsigned st = stage ? smem_u32(&stg[1][0]) : smem_u32(&stg[0][0]);
                mbar_expect_tx(mb, bytes);
                bulk_copy(st, s4 + (long long)c2 * CH, bytes, mb);
            }
        }
    }

    // ---- last-finishing block validates (exact fallback only if speculation failed)
    __shared__ int s_last;
    __syncthreads();
    if (t == 0) {
        __threadfence();
        unsigned d = atomicAdd(&g_done1, 1u);
        s_last = (d == gridDim.x - 1) ? 1 : 0;
    }
    __syncthreads();
    if (!s_last) return;

    __shared__ int s_fb;
    if (t == 0) {
        g_done1 = 0;
        int c = g_candCount;
        s_fb = (c < MM || c > CAND);
        if (!s_fb) { g_cnt = c; g_nValid = MM; g_edgeCount = 0; }
    }
    __syncthreads();
    if (!s_fb) return;

    // pathological fallback: exact histogram selection (reuse stage memory as hist)
    unsigned* sh = (unsigned*)&stg[0][0];  // 4096 entries = 16 KB
    __shared__ unsigned s_cut;
    __shared__ int s_cnt2;
    for (int i = t; i < NB; i += 1024) sh[i] = 0u;
    __syncthreads();
    for (int i = t; i < n; i += 1024) {
        float v = score[i].y;
        if (v > 0.5f) {
            unsigned u = __float_as_uint(v);
            unsigned b = (u - 0x3F000000u) >> 11;
            if (b > NB - 1u) b = NB - 1u;
            atomicAdd(&sh[b], 1u);
        }
    }
    __syncthreads();
    if (t == 0) {
        unsigned run = 0; unsigned cut = 0;
        for (int b = NB - 1; b >= 0; b--) {
            run += sh[b];
            if (run >= (unsigned)MM) { cut = (unsigned)b; break; }
        }
        s_cut = cut;
        s_cnt2 = 0;
    }
    __syncthreads();
    unsigned cut = s_cut;
    for (int i = t; i < n; i += 1024) {
        float v = score[i].y;
        if (v > 0.5f) {
            unsigned u = __float_as_uint(v);
            unsigned b = (u - 0x3F000000u) >> 11;
            if (b > NB - 1u) b = NB - 1u;
            if (b >= cut) {
                int pos = atomicAdd(&s_cnt2, 1);
                if (pos < CAND)
                    g_cand[pos] = ((unsigned long long)u << 32) |
                                  (unsigned long long)(0xFFFFFFFFu - (unsigned)i);
            }
        }
    }
    __syncthreads();
    if (t == 0) {
        int c2 = s_cnt2; if (c2 > CAND) c2 = CAND;
        g_cnt = c2;
        g_nValid = (c2 < MM) ? c2 : MM;
        g_edgeCount = 0;
    }
}

// ---------------- k_rank: warp-per-candidate rank-by-count + fused decode --------
__global__ __launch_bounds__(1024) void k_rank(const float4* __restrict__ anchors,
                                               const float4* __restrict__ deltas) {
    __shared__ unsigned long long keys[CAND]; // 32 KB
    int cnt = g_cnt;
    int t = threadIdx.x;
    if ((int)blockIdx.x * 32 >= cnt) return;
    int cntR = (cnt + 127) & ~127;            // runtime loop bound, 128-aligned
    for (int i = t; i < cntR; i += 1024) keys[i] = (i < cnt) ? g_cand[i] : 0ULL;
    __syncthreads();
    int gw = blockIdx.x * 32 + (t >> 5);
    int lane = t & 31;
    if (gw >= cnt) return;
    unsigned long long my = keys[gw];
    int g = 0;
    for (int base = 0; base < cntR; base += 128) {
        unsigned long long k0 = keys[base       + lane];
        unsigned long long k1 = keys[base +  32 + lane];
        unsigned long long k2 = keys[base +  64 + lane];
        unsigned long long k3 = keys[base +  96 + lane];
        g += __popc(__ballot_sync(0xffffffffu, k0 > my));
        g += __popc(__ballot_sync(0xffffffffu, k1 > my));
        g += __popc(__ballot_sync(0xffffffffu, k2 > my));
        g += __popc(__ballot_sync(0xffffffffu, k3 > my));
    }
    if (lane == 0 && g < MM) {
        unsigned idx = 0xFFFFFFFFu - (unsigned)(my & 0xFFFFFFFFull);
        float4 a = __ldg(anchors + idx);
        float4 d = __ldg(deltas + idx);
        float w  = a.z - a.x;
        float h  = a.w - a.y;
        float cx = a.x + 0.5f * w;
        float cy = a.y + 0.5f * h;
        float ncx = cx + d.x * w;
        float ncy = cy + d.y * h;
        float nw  = w * expf(d.z);
        float nh  = h * expf(d.w);
        float x1 = ncx - 0.5f * nw, y1 = ncy - 0.5f * nh;
        float x2 = ncx + 0.5f * nw, y2 = ncy + 0.5f * nh;
        x1 = fminf(fmaxf(x1, 0.f), 1024.f);
        y1 = fminf(fmaxf(y1, 0.f), 1024.f);
        x2 = fminf(fmaxf(x2, 0.f), 1024.f);
        y2 = fminf(fmaxf(y2, 0.f), 1024.f);
        bool big = ((x2 - x1) >= 1.0f) && ((y2 - y1) >= 1.0f);
        g_boxes[g] = make_float4(x1, y1, x2, y2);
        g_keep0[g] = big ? 1 : 0;
    }
}

// ---------------- k_pairs: one block per 32x32 upper-triangle tile, one pair per
//                  thread; last-finishing block runs the NMS finalize epilogue ----
__global__ __launch_bounds__(1024) void k_pairs(float* __restrict__ out) {
    int t = threadIdx.x; // 1024
    int nV = g_nValid;

    {
        int tile = blockIdx.x;
        int bx = 0, rem = tile;
        while (rem >= NT - bx) { rem -= NT - bx; bx++; }
        int by = bx + rem;
        int i = bx * TB + (t >> 5);
        int j = by * TB + (t & 31);
        if (i < nV && j < nV && j > i && g_keep0[i] && g_keep0[j]) {
            float4 A = g_boxes[i];   // warp-uniform -> L1 broadcast
            float4 B = g_boxes[j];   // coalesced across lanes
            float ai = (A.z - A.x) * (A.w - A.y);
            float aj = (B.z - B.x) * (B.w - B.y);
            float ltx = fmaxf(A.x, B.x), lty = fmaxf(A.y, B.y);
            float rbx = fminf(A.z, B.z), rby = fminf(A.w, B.w);
            float iw = fmaxf(rbx - ltx, 0.f), ih = fmaxf(rby - lty, 0.f);
            float inter = iw * ih;
            float iou = inter / (ai + aj - inter + 1e-9f);
            if (iou > 0.7f) {
                int pos = atomicAdd(&g_edgeCount, 1);
                if (pos < EDGE_MAX) g_edges[pos] = ((unsigned)i << 16) | (unsigned)j;
            }
        }
    }

    // ---- last-finishing block runs finalize ----
    __shared__ int s_last;
    __syncthreads();
    if (t == 0) {
        __threadfence();
        unsigned d = atomicAdd(&g_done2, 1u);
        s_last = (d == gridDim.x - 1) ? 1 : 0;
    }
    __syncthreads();
    if (!s_last) return;

    __shared__ unsigned char dead[MM];
    __shared__ unsigned se[EDGE_MAX]; // 16 KB
    for (int m = t; m < MM; m += 1024) dead[m] = (m < nV && g_keep0[m]) ? 0 : 1;
    int ec = g_edgeCount; if (ec > EDGE_MAX) ec = EDGE_MAX;
    for (int i = t; i < EDGE_MAX; i += 1024) se[i] = (i < ec) ? g_edges[i] : 0xFFFFFFFFu;
    __syncthreads();

    if (ec > 256) {
        for (int k = 2; k <= EDGE_MAX; k <<= 1) {
            for (int j = k >> 1; j > 0; j >>= 1) {
                for (int i = t; i < EDGE_MAX; i += 1024) {
                    int ixj = i ^ j;
                    if (ixj > i) {
                        unsigned a = se[i], b = se[ixj];
                        bool up = ((i & k) == 0);
                        if (up ? (a > b) : (a < b)) { se[i] = b; se[ixj] = a; }
                    }
                }
                __syncthreads();
            }
        }
    } else if (t == 0) {
        for (int a = 1; a < ec; a++) {
            unsigned key = se[a];
            int b = a - 1;
            while (b >= 0 && se[b] > key) { se[b + 1] = se[b]; b--; }
            se[b + 1] = key;
        }
    }
    __syncthreads();

    if (t == 0) {
        for (int e = 0; e < ec; e++) {
            unsigned u = se[e];
            int i = (int)(u >> 16), j = (int)(u & 0xFFFFu);
            if (!dead[i]) dead[j] = 1;
        }
    }
    __syncthreads();

    for (int m = t; m < MM; m += 1024) {
        bool keep = (dead[m] == 0);
        float4 b = g_boxes[m];
        out[m * 4 + 0] = keep ? b.x : 0.f;
        out[m * 4 + 1] = keep ? b.y : 0.f;
        out[m * 4 + 2] = keep ? b.z : 0.f;
        out[m * 4 + 3] = keep ? b.w : 0.f;
        out[MM * 4 + m] = keep ? 1.f : 0.f;
    }
    __syncthreads();
    if (t == 0) {   // reset for next replay
        g_candCount = 0;
        g_edgeCount = 0;
        g_done2 = 0;
    }
}

// ---------------- launch ----------------
extern "C" void kernel_launch(void* const* d_in, const int* in_sizes, int n_in,
                              void* d_out, int out_size) {
    int si = 0;
    for (int i = 1; i < n_in; i++) if (in_sizes[i] < in_sizes[si]) si = i;
    int others[2], o = 0;
    for (int i = 0; i < n_in && o < 2; i++) if (i != si) others[o++] = i;

    const float4* anchors = (const float4*)d_in[others[0]];
    const float2* score   = (const float2*)d_in[si];
    const float4* deltas  = (const float4*)d_in[others[1]];
    int n  = in_sizes[si] / 2;
    int n4 = in_sizes[si] / 4;

    k_main<<<296, 1024>>>((const float4*)score, n4, score, n);
    k_rank<<<CAND / 32, 1024>>>(anchors, deltas);
    k_pairs<<<NTILES, 1024>>>((float*)d_out);
}

// round 10
// speedup vs baseline: 1.3609x; 1.2470x over previous
#include <cuda_runtime.h>
#include <math.h>

#define MM 2000
#define NB 4096
#define CAND 4096
#define EDGE_MAX 4096
#define T_STATIC 0.9994f
#define TB 64
#define NT ((MM + TB - 1) / TB)        // 32 tiles per dim
#define NTILES (NT * (NT + 1) / 2)     // 528 upper-triangle tiles

// ---------------- device scratch (zero-initialized at module load) ----------------
__device__ int                g_candCount;
__device__ int                g_cnt;
__device__ int                g_nValid;
__device__ int                g_edgeCount;
__device__ unsigned           g_done1, g_done2;
__device__ unsigned long long g_cand[CAND];
__device__ float4             g_boxes[MM];
__device__ int                g_keep0[MM];
__device__ unsigned int       g_edges[EDGE_MAX];

// ---------------- k_main: streaming speculative compact + last-block validation --
__global__ __launch_bounds__(1024) void k_main(const float4* __restrict__ s4, int n4,
                                               const float2* __restrict__ score, int n) {
    int nthr = gridDim.x * blockDim.x;
    int tid  = blockIdx.x * blockDim.x + threadIdx.x;
    for (int i = tid; i < n4; i += 4 * nthr) {
        int i1 = i + nthr, i2 = i + 2 * nthr, i3 = i + 3 * nthr;
        bool b1 = i1 < n4, b2 = i2 < n4, b3 = i3 < n4;
        float4 a0 = s4[i];
        float4 a1, a2, a3;
        if (b1) a1 = s4[i1];
        if (b2) a2 = s4[i2];
        if (b3) a3 = s4[i3];
        #define EMIT(v, idx)                                                        \
            if ((v) > T_STATIC) {                                                   \
                int pos = atomicAdd(&g_candCount, 1);                               \
                if (pos < CAND)                                                     \
                    g_cand[pos] = ((unsigned long long)__float_as_uint(v) << 32) |  \
                                  (unsigned long long)(0xFFFFFFFFu - (idx));        \
            }
        EMIT(a0.y, 2u * (unsigned)i)
        EMIT(a0.w, 2u * (unsigned)i + 1u)
        if (b1) { EMIT(a1.y, 2u * (unsigned)i1) EMIT(a1.w, 2u * (unsigned)i1 + 1u) }
        if (b2) { EMIT(a2.y, 2u * (unsigned)i2) EMIT(a2.w, 2u * (unsigned)i2 + 1u) }
        if (b3) { EMIT(a3.y, 2u * (unsigned)i3) EMIT(a3.w, 2u * (unsigned)i3 + 1u) }
        #undef EMIT
    }

    // ---- last-finishing block validates (exact fallback only if speculation failed)
    __shared__ int s_last;
    __syncthreads();
    if (threadIdx.x == 0) {
        __threadfence();
        unsigned d = atomicAdd(&g_done1, 1u);
        s_last = (d == gridDim.x - 1) ? 1 : 0;
    }
    __syncthreads();
    if (!s_last) return;

    int t = threadIdx.x;
    __shared__ int s_fb;
    if (t == 0) {
        g_done1 = 0;
        int c = g_candCount;
        s_fb = (c < MM || c > CAND);
        if (!s_fb) { g_cnt = c; g_nValid = MM; g_edgeCount = 0; }
    }
    __syncthreads();
    if (!s_fb) return;

    // pathological fallback: exact histogram selection by this one block
    __shared__ unsigned sh[NB];
    __shared__ unsigned s_cut;
    __shared__ int s_cnt2;
    for (int i = t; i < NB; i += 1024) sh[i] = 0u;
    __syncthreads();
    for (int i = t; i < n; i += 1024) {
        float v = score[i].y;
        if (v > 0.5f) {
            unsigned u = __float_as_uint(v);
            unsigned b = (u - 0x3F000000u) >> 11;
            if (b > NB - 1u) b = NB - 1u;
            atomicAdd(&sh[b], 1u);
        }
    }
    __syncthreads();
    if (t == 0) {
        unsigned run = 0; unsigned cut = 0;
        for (int b = NB - 1; b >= 0; b--) {
            run += sh[b];
            if (run >= (unsigned)MM) { cut = (unsigned)b; break; }
        }
        s_cut = cut;
        s_cnt2 = 0;
    }
    __syncthreads();
    unsigned cut = s_cut;
    for (int i = t; i < n; i += 1024) {
        float v = score[i].y;
        if (v > 0.5f) {
            unsigned u = __float_as_uint(v);
            unsigned b = (u - 0x3F000000u) >> 11;
            if (b > NB - 1u) b = NB - 1u;
            if (b >= cut) {
                int pos = atomicAdd(&s_cnt2, 1);
                if (pos < CAND)
                    g_cand[pos] = ((unsigned long long)u << 32) |
                                  (unsigned long long)(0xFFFFFFFFu - (unsigned)i);
            }
        }
    }
    __syncthreads();
    if (t == 0) {
        int c2 = s_cnt2; if (c2 > CAND) c2 = CAND;
        g_cnt = c2;
        g_nValid = (c2 < MM) ? c2 : MM;
        g_edgeCount = 0;
    }
}

// ---------------- k_rank: warp-per-candidate rank-by-count + fused decode --------
// Runtime-bounded scan: ~cnt/128 iterations (cnt ~= 2400 at T_STATIC=0.9994).
__global__ __launch_bounds__(1024) void k_rank(const float4* __restrict__ anchors,
                                               const float4* __restrict__ deltas) {
    __shared__ unsigned long long keys[CAND]; // 32 KB
    int cnt = g_cnt;
    int t = threadIdx.x;
    if ((int)blockIdx.x * 32 >= cnt) return;
    int cntR = (cnt + 127) & ~127;
    for (int i = t; i < cntR; i += 1024) keys[i] = (i < cnt) ? g_cand[i] : 0ULL;
    __syncthreads();
    int gw = blockIdx.x * 32 + (t >> 5);
    int lane = t & 31;
    if (gw >= cnt) return;
    unsigned long long my = keys[gw];
    int g = 0;
    for (int base = 0; base < cntR; base += 128) {
        unsigned long long k0 = keys[base       + lane];
        unsigned long long k1 = keys[base +  32 + lane];
        unsigned long long k2 = keys[base +  64 + lane];
        unsigned long long k3 = keys[base +  96 + lane];
        g += __popc(__ballot_sync(0xffffffffu, k0 > my));
        g += __popc(__ballot_sync(0xffffffffu, k1 > my));
        g += __popc(__ballot_sync(0xffffffffu, k2 > my));
        g += __popc(__ballot_sync(0xffffffffu, k3 > my));
    }
    if (lane == 0 && g < MM) {
        unsigned idx = 0xFFFFFFFFu - (unsigned)(my & 0xFFFFFFFFull);
        float4 a = __ldg(anchors + idx);
        float4 d = __ldg(deltas + idx);
        float w  = a.z - a.x;
        float h  = a.w - a.y;
        float cx = a.x + 0.5f * w;
        float cy = a.y + 0.5f * h;
        float ncx = cx + d.x * w;
        float ncy = cy + d.y * h;
        float nw  = w * expf(d.z);
        float nh  = h * expf(d.w);
        float x1 = ncx - 0.5f * nw, y1 = ncy - 0.5f * nh;
        float x2 = ncx + 0.5f * nw, y2 = ncy + 0.5f * nh;
        x1 = fminf(fmaxf(x1, 0.f), 1024.f);
        y1 = fminf(fmaxf(y1, 0.f), 1024.f);
        x2 = fminf(fmaxf(x2, 0.f), 1024.f);
        y2 = fminf(fmaxf(y2, 0.f), 1024.f);
        bool big = ((x2 - x1) >= 1.0f) && ((y2 - y1) >= 1.0f);
        g_boxes[g] = make_float4(x1, y1, x2, y2);
        g_keep0[g] = big ? 1 : 0;
    }
}

// ---------------- k_pairs: 64x64 tile per block (528 blocks), 4 pairs/thread;
//                  last-finishing block runs the NMS finalize epilogue -----------
__global__ __launch_bounds__(1024) void k_pairs(float* __restrict__ out) {
    __shared__ float4 bjs[TB];
    __shared__ float  ajs[TB];
    __shared__ int    kjs[TB];
    int t = threadIdx.x; // 1024
    int nV = g_nValid;

    {
        int tile = blockIdx.x;
        int bx = 0, rem = tile;
        while (rem >= NT - bx) { rem -= NT - bx; bx++; }
        int by = bx + rem;

        if (t < TB) {
            int j = by * TB + t;
            if (j < nV) {
                float4 b = g_boxes[j];
                bjs[t] = b; ajs[t] = (b.z - b.x) * (b.w - b.y); kjs[t] = g_keep0[j];
            } else kjs[t] = 0;
        }
        __syncthreads();

        int li = t >> 4;                    // 64 rows, 16 threads each
        int i  = bx * TB + li;
        if (i < nV && g_keep0[i]) {
            float4 A = g_boxes[i];          // broadcast across the 16 row-threads
            float ai = (A.z - A.x) * (A.w - A.y);
            int ljBase = (t & 15) * 4;
            int jBase  = by * TB + ljBase;
            #pragma unroll
            for (int u = 0; u < 4; u++) {
                int lj = ljBase + u;
                int j  = jBase + u;
                if (j > i && j < nV && kjs[lj]) {
                    float4 B = bjs[lj];
                    float ltx = fmaxf(A.x, B.x), lty = fmaxf(A.y, B.y);
                    float rbx = fminf(A.z, B.z), rby = fminf(A.w, B.w);
                    float iw = fmaxf(rbx - ltx, 0.f), ih = fmaxf(rby - lty, 0.f);
                    float inter = iw * ih;
                    float iou = inter / (ai + ajs[lj] - inter + 1e-9f);
                    if (iou > 0.7f) {
                        int pos = atomicAdd(&g_edgeCount, 1);
                        if (pos < EDGE_MAX) g_edges[pos] = ((unsigned)i << 16) | (unsigned)j;
                    }
                }
            }
        }
    }

    // ---- last-finishing block runs finalize ----
    __shared__ int s_last;
    __syncthreads();
    if (t == 0) {
        __threadfence();
        unsigned d = atomicAdd(&g_done2, 1u);
        s_last = (d == gridDim.x - 1) ? 1 : 0;
    }
    __syncthreads();
    if (!s_last) return;

    __shared__ unsigned char dead[MM];
    __shared__ unsigned se[EDGE_MAX]; // 16 KB
    for (int m = t; m < MM; m += 1024) dead[m] = (m < nV && g_keep0[m]) ? 0 : 1;
    int ec = g_edgeCount; if (ec > EDGE_MAX) ec = EDGE_MAX;
    for (int i = t; i < EDGE_MAX; i += 1024) se[i] = (i < ec) ? g_edges[i] : 0xFFFFFFFFu;
    __syncthreads();

    if (ec > 256) {
        for (int k = 2; k <= EDGE_MAX; k <<= 1) {
            for (int j = k >> 1; j > 0; j >>= 1) {
                for (int i = t; i < EDGE_MAX; i += 1024) {
                    int ixj = i ^ j;
                    if (ixj > i) {
                        unsigned a = se[i], b = se[ixj];
                        bool up = ((i & k) == 0);
                        if (up ? (a > b) : (a < b)) { se[i] = b; se[ixj] = a; }
                    }
                }
                __syncthreads();
            }
        }
    } else if (t == 0) {
        for (int a = 1; a < ec; a++) {
            unsigned key = se[a];
            int b = a - 1;
            while (b >= 0 && se[b] > key) { se[b + 1] = se[b]; b--; }
            se[b + 1] = key;
        }
    }
    __syncthreads();

    if (t == 0) {
        for (int e = 0; e < ec; e++) {
            unsigned u = se[e];
            int i = (int)(u >> 16), j = (int)(u & 0xFFFFu);
            if (!dead[i]) dead[j] = 1;
        }
    }
    __syncthreads();

    for (int m = t; m < MM; m += 1024) {
        bool keep = (dead[m] == 0);
        float4 b = g_boxes[m];
        out[m * 4 + 0] = keep ? b.x : 0.f;
        out[m * 4 + 1] = keep ? b.y : 0.f;
        out[m * 4 + 2] = keep ? b.z : 0.f;
        out[m * 4 + 3] = keep ? b.w : 0.f;
        out[MM * 4 + m] = keep ? 1.f : 0.f;
    }
    __syncthreads();
    if (t == 0) {   // reset for next replay
        g_candCount = 0;
        g_edgeCount = 0;
        g_done2 = 0;
    }
}

// ---------------- launch ----------------
extern "C" void kernel_launch(void* const* d_in, const int* in_sizes, int n_in,
                              void* d_out, int out_size) {
    int si = 0;
    for (int i = 1; i < n_in; i++) if (in_sizes[i] < in_sizes[si]) si = i;
    int others[2], o = 0;
    for (int i = 0; i < n_in && o < 2; i++) if (i != si) others[o++] = i;

    const float4* anchors = (const float4*)d_in[others[0]];
    const float2* score   = (const float2*)d_in[si];
    const float4* deltas  = (const float4*)d_in[others[1]];
    int n  = in_sizes[si] / 2;
    int n4 = in_sizes[si] / 4;

    k_main<<<296, 1024>>>((const float4*)score, n4, score, n);
    k_rank<<<CAND / 32, 1024>>>(anchors, deltas);
    k_pairs<<<NTILES, 1024>>>((float*)d_out);
}

// round 11
// speedup vs baseline: 1.6460x; 1.2095x over previous
#include <cuda_runtime.h>
#include <math.h>

#define MM 2000
#define NB 4096
#define CAND 4096
#define EDGE_MAX 4096
#define T_STATIC 0.9994f
#define TB 64
#define NT ((MM + TB - 1) / TB)        // 32 tiles per dim
#define NTILES (NT * (NT + 1) / 2)     // 528 upper-triangle tiles
#define GRID 296                       // 2 CTAs/SM x 148 SMs — fully co-resident

// ---------------- device scratch (zero-initialized at module load) ----------------
__device__ int                g_candCount;
__device__ int                g_cnt;
__device__ int                g_nValid;
__device__ int                g_edgeCount;
__device__ unsigned           g_done1, g_done2;
__device__ unsigned long long g_cand[CAND];
__device__ float4             g_boxes[MM];
__device__ int                g_keep0[MM];
__device__ unsigned int       g_edges[EDGE_MAX];
__device__ volatile unsigned  g_gen;
__device__ unsigned           g_arrive;

// ---------------- k_main: streaming speculative compact + last-block validation --
__global__ __launch_bounds__(1024) void k_main(const float4* __restrict__ s4, int n4,
                                               const float2* __restrict__ score, int n) {
    int nthr = gridDim.x * blockDim.x;
    int tid  = blockIdx.x * blockDim.x + threadIdx.x;
    for (int i = tid; i < n4; i += 4 * nthr) {
        int i1 = i + nthr, i2 = i + 2 * nthr, i3 = i + 3 * nthr;
        bool b1 = i1 < n4, b2 = i2 < n4, b3 = i3 < n4;
        float4 a0 = s4[i];
        float4 a1, a2, a3;
        if (b1) a1 = s4[i1];
        if (b2) a2 = s4[i2];
        if (b3) a3 = s4[i3];
        #define EMIT(v, idx)                                                        \
            if ((v) > T_STATIC) {                                                   \
                int pos = atomicAdd(&g_candCount, 1);                               \
                if (pos < CAND)                                                     \
                    g_cand[pos] = ((unsigned long long)__float_as_uint(v) << 32) |  \
                                  (unsigned long long)(0xFFFFFFFFu - (idx));        \
            }
        EMIT(a0.y, 2u * (unsigned)i)
        EMIT(a0.w, 2u * (unsigned)i + 1u)
        if (b1) { EMIT(a1.y, 2u * (unsigned)i1) EMIT(a1.w, 2u * (unsigned)i1 + 1u) }
        if (b2) { EMIT(a2.y, 2u * (unsigned)i2) EMIT(a2.w, 2u * (unsigned)i2 + 1u) }
        if (b3) { EMIT(a3.y, 2u * (unsigned)i3) EMIT(a3.w, 2u * (unsigned)i3 + 1u) }
        #undef EMIT
    }

    // ---- last-finishing block validates (exact fallback only if speculation failed)
    __shared__ int s_last;
    __syncthreads();
    if (threadIdx.x == 0) {
        __threadfence();
        unsigned d = atomicAdd(&g_done1, 1u);
        s_last = (d == gridDim.x - 1) ? 1 : 0;
    }
    __syncthreads();
    if (!s_last) return;

    int t = threadIdx.x;
    __shared__ int s_fb;
    if (t == 0) {
        g_done1 = 0;
        int c = g_candCount;
        s_fb = (c < MM || c > CAND);
        if (!s_fb) { g_cnt = c; g_nValid = MM; g_edgeCount = 0; }
    }
    __syncthreads();
    if (!s_fb) return;

    // pathological fallback: exact histogram selection by this one block
    __shared__ unsigned sh[NB];
    __shared__ unsigned s_cut;
    __shared__ int s_cnt2;
    for (int i = t; i < NB; i += 1024) sh[i] = 0u;
    __syncthreads();
    for (int i = t; i < n; i += 1024) {
        float v = score[i].y;
        if (v > 0.5f) {
            unsigned u = __float_as_uint(v);
            unsigned b = (u - 0x3F000000u) >> 11;
            if (b > NB - 1u) b = NB - 1u;
            atomicAdd(&sh[b], 1u);
        }
    }
    __syncthreads();
    if (t == 0) {
        unsigned run = 0; unsigned cut = 0;
        for (int b = NB - 1; b >= 0; b--) {
            run += sh[b];
            if (run >= (unsigned)MM) { cut = (unsigned)b; break; }
        }
        s_cut = cut;
        s_cnt2 = 0;
    }
    __syncthreads();
    unsigned cut = s_cut;
    for (int i = t; i < n; i += 1024) {
        float v = score[i].y;
        if (v > 0.5f) {
            unsigned u = __float_as_uint(v);
            unsigned b = (u - 0x3F000000u) >> 11;
            if (b > NB - 1u) b = NB - 1u;
            if (b >= cut) {
                int pos = atomicAdd(&s_cnt2, 1);
                if (pos < CAND)
                    g_cand[pos] = ((unsigned long long)u << 32) |
                                  (unsigned long long)(0xFFFFFFFFu - (unsigned)i);
            }
        }
    }
    __syncthreads();
    if (t == 0) {
        int c2 = s_cnt2; if (c2 > CAND) c2 = CAND;
        g_cnt = c2;
        g_nValid = (c2 < MM) ? c2 : MM;
        g_edgeCount = 0;
    }
}

// ---------------- grid barrier (all GRID blocks resident by construction) --------
__device__ __forceinline__ void grid_barrier() {
    __syncthreads();
    if (threadIdx.x == 0) {
        __threadfence();
        unsigned gen = g_gen;
        if (atomicAdd(&g_arrive, 1u) == (unsigned)gridDim.x - 1u) {
            atomicExch(&g_arrive, 0u);
            __threadfence();
            g_gen = gen + 1u;
        } else {
            while (g_gen == gen) __nanosleep(64);
        }
        __threadfence();
    }
    __syncthreads();
}

// ---------------- k_post: rank+decode | barrier | pairs | finalize ---------------
__global__ void __launch_bounds__(1024, 2) k_post(const float4* __restrict__ anchors,
                                                  const float4* __restrict__ deltas,
                                                  float* __restrict__ out) {
    __shared__ union {
        unsigned long long keys[CAND];                                  // 32 KB (rank)
        struct { unsigned se[EDGE_MAX]; unsigned se2[EDGE_MAX];
                 unsigned char dead[MM]; } fin;                         // 34.4 KB
    } sh;
    __shared__ float4 bjs[TB];
    __shared__ float  ajs[TB];
    __shared__ int    kjs[TB];
    int t = threadIdx.x;
    int cnt = g_cnt;
    int nV  = g_nValid;

    // ========== Phase A: warp-per-candidate rank + fused decode ==========
    if ((int)blockIdx.x * 32 < cnt) {
        int cntR = (cnt + 127) & ~127;
        for (int i = t; i < cntR; i += 1024) sh.keys[i] = (i < cnt) ? g_cand[i] : 0ULL;
        __syncthreads();
        int gw = blockIdx.x * 32 + (t >> 5);
        int lane = t & 31;
        if (gw < cnt) {
            unsigned long long my = sh.keys[gw];
            int g = 0;
            for (int base = 0; base < cntR; base += 128) {
                unsigned long long k0 = sh.keys[base       + lane];
                unsigned long long k1 = sh.keys[base +  32 + lane];
                unsigned long long k2 = sh.keys[base +  64 + lane];
                unsigned long long k3 = sh.keys[base +  96 + lane];
                g += __popc(__ballot_sync(0xffffffffu, k0 > my));
                g += __popc(__ballot_sync(0xffffffffu, k1 > my));
                g += __popc(__ballot_sync(0xffffffffu, k2 > my));
                g += __popc(__ballot_sync(0xffffffffu, k3 > my));
            }
            if (lane == 0 && g < MM) {
                unsigned idx = 0xFFFFFFFFu - (unsigned)(my & 0xFFFFFFFFull);
                float4 a = __ldg(anchors + idx);
                float4 d = __ldg(deltas + idx);
                float w  = a.z - a.x;
                float h  = a.w - a.y;
                float cx = a.x + 0.5f * w;
                float cy = a.y + 0.5f * h;
                float ncx = cx + d.x * w;
                float ncy = cy + d.y * h;
                float nw  = w * expf(d.z);
                float nh  = h * expf(d.w);
                float x1 = ncx - 0.5f * nw, y1 = ncy - 0.5f * nh;
                float x2 = ncx + 0.5f * nw, y2 = ncy + 0.5f * nh;
                x1 = fminf(fmaxf(x1, 0.f), 1024.f);
                y1 = fminf(fmaxf(y1, 0.f), 1024.f);
                x2 = fminf(fmaxf(x2, 0.f), 1024.f);
                y2 = fminf(fmaxf(y2, 0.f), 1024.f);
                bool big = ((x2 - x1) >= 1.0f) && ((y2 - y1) >= 1.0f);
                g_boxes[g] = make_float4(x1, y1, x2, y2);
                g_keep0[g] = big ? 1 : 0;
            }
        }
    }

    grid_barrier();   // all boxes/keep0 visible chip-wide

    // ========== Phase B: pairs — 64x64 tiles strided over the grid ==========
    for (int tile = blockIdx.x; tile < NTILES; tile += gridDim.x) {
        int bx = 0, rem = tile;
        while (rem >= NT - bx) { rem -= NT - bx; bx++; }
        int by = bx + rem;

        __syncthreads();                    // protect bjs from previous iteration
        if (t < TB) {
            int j = by * TB + t;
            if (j < nV) {
                float4 b = g_boxes[j];
                bjs[t] = b; ajs[t] = (b.z - b.x) * (b.w - b.y); kjs[t] = g_keep0[j];
            } else kjs[t] = 0;
        }
        __syncthreads();

        int li = t >> 4;
        int i  = bx * TB + li;
        if (i < nV && g_keep0[i]) {
            float4 A = g_boxes[i];
            float ai = (A.z - A.x) * (A.w - A.y);
            int ljBase = (t & 15) * 4;
            int jBase  = by * TB + ljBase;
            #pragma unroll
            for (int u = 0; u < 4; u++) {
                int lj = ljBase + u;
                int j  = jBase + u;
                if (j > i && j < nV && kjs[lj]) {
                    float4 B = bjs[lj];
                    float ltx = fmaxf(A.x, B.x), lty = fmaxf(A.y, B.y);
                    float rbx = fminf(A.z, B.z), rby = fminf(A.w, B.w);
                    float iw = fmaxf(rbx - ltx, 0.f), ih = fmaxf(rby - lty, 0.f);
                    float inter = iw * ih;
                    float iou = inter / (ai + ajs[lj] - inter + 1e-9f);
                    if (iou > 0.7f) {
                        int pos = atomicAdd(&g_edgeCount, 1);
                        if (pos < EDGE_MAX) g_edges[pos] = ((unsigned)i << 16) | (unsigned)j;
                    }
                }
            }
        }
    }

    // ========== last-finishing block: finalize ==========
    __shared__ int s_last;
    __syncthreads();
    if (t == 0) {
        __threadfence();
        unsigned d = atomicAdd(&g_done2, 1u);
        s_last = (d == gridDim.x - 1) ? 1 : 0;
    }
    __syncthreads();
    if (!s_last) return;

    for (int m = t; m < MM; m += 1024) sh.fin.dead[m] = (m < nV && g_keep0[m]) ? 0 : 1;
    int ec = g_edgeCount; if (ec > EDGE_MAX) ec = EDGE_MAX;
    for (int i = t; i < ec; i += 1024) sh.fin.se[i] = g_edges[i];
    __syncthreads();

    // parallel counting-rank sort: distinct (i<<16|j) keys, O(ec^2/1024)
    for (int e = t; e < ec; e += 1024) {
        unsigned key = sh.fin.se[e];
        int r = 0;
        for (int f = 0; f < ec; f++) r += (sh.fin.se[f] < key) ? 1 : 0;
        sh.fin.se2[r] = key;
    }
    __syncthreads();

    if (t == 0) {
        // greedy NMS: edges sorted by (suppressor, suppressee); suppressor must be alive
        for (int e = 0; e < ec; e++) {
            unsigned u = sh.fin.se2[e];
            int i = (int)(u >> 16), j = (int)(u & 0xFFFFu);
            if (!sh.fin.dead[i]) sh.fin.dead[j] = 1;
        }
    }
    __syncthreads();

    for (int m = t; m < MM; m += 1024) {
        bool keep = (sh.fin.dead[m] == 0);
        float4 b = g_boxes[m];
        out[m * 4 + 0] = keep ? b.x : 0.f;
        out[m * 4 + 1] = keep ? b.y : 0.f;
        out[m * 4 + 2] = keep ? b.z : 0.f;
        out[m * 4 + 3] = keep ? b.w : 0.f;
        out[MM * 4 + m] = keep ? 1.f : 0.f;
    }
    __syncthreads();
    if (t == 0) {   // reset for next replay
        g_candCount = 0;
        g_edgeCount = 0;
        g_done2 = 0;
    }
}

// ---------------- launch ----------------
extern "C" void kernel_launch(void* const* d_in, const int* in_sizes, int n_in,
                              void* d_out, int out_size) {
    int si = 0;
    for (int i = 1; i < n_in; i++) if (in_sizes[i] < in_sizes[si]) si = i;
    int others[2], o = 0;
    for (int i = 0; i < n_in && o < 2; i++) if (i != si) others[o++] = i;

    const float4* anchors = (const float4*)d_in[others[0]];
    const float2* score   = (const float2*)d_in[si];
    const float4* deltas  = (const float4*)d_in[others[1]];
    int n  = in_sizes[si] / 2;
    int n4 = in_sizes[si] / 4;

    k_main<<<296, 1024>>>((const float4*)score, n4, score, n);
    k_post<<<GRID, 1024>>>(anchors, deltas, (float*)d_out);
}

// round 12
// speedup vs baseline: 1.6686x; 1.0138x over previous
#include <cuda_runtime.h>
#include <math.h>

#define MM 2000
#define NB 4096
#define CAND 4096
#define EDGE_MAX 4096
#define T_STATIC 0.9994f
#define TB 64
#define NT ((MM + TB - 1) / TB)        // 32 tiles per dim
#define NTILES (NT * (NT + 1) / 2)     // 528 upper-triangle tiles
#define GRID 296                       // 2 CTAs/SM x 148 SMs — fully co-resident

// ---------------- device scratch (zero-initialized at module load) ----------------
__device__ int                g_candCount;
__device__ int                g_cnt;
__device__ int                g_nValid;
__device__ int                g_edgeCount;
__device__ unsigned           g_done1, g_done2;
__device__ unsigned long long g_cand[CAND];
__device__ float4             g_boxes[MM];
__device__ int                g_keep0[MM];
__device__ unsigned int       g_edges[EDGE_MAX];
__device__ volatile unsigned  g_gen;
__device__ unsigned           g_arrive;

// ---------------- k_main: streaming speculative compact + last-block validation --
__global__ __launch_bounds__(1024) void k_main(const float4* __restrict__ s4, int n4,
                                               const float2* __restrict__ score, int n) {
    int nthr = gridDim.x * blockDim.x;
    int tid  = blockIdx.x * blockDim.x + threadIdx.x;
    for (int i = tid; i < n4; i += 4 * nthr) {
        int i1 = i + nthr, i2 = i + 2 * nthr, i3 = i + 3 * nthr;
        bool b1 = i1 < n4, b2 = i2 < n4, b3 = i3 < n4;
        float4 a0 = s4[i];
        float4 a1, a2, a3;
        if (b1) a1 = s4[i1];
        if (b2) a2 = s4[i2];
        if (b3) a3 = s4[i3];
        #define EMIT(v, idx)                                                        \
            if ((v) > T_STATIC) {                                                   \
                int pos = atomicAdd(&g_candCount, 1);                               \
                if (pos < CAND)                                                     \
                    g_cand[pos] = ((unsigned long long)__float_as_uint(v) << 32) |  \
                                  (unsigned long long)(0xFFFFFFFFu - (idx));        \
            }
        EMIT(a0.y, 2u * (unsigned)i)
        EMIT(a0.w, 2u * (unsigned)i + 1u)
        if (b1) { EMIT(a1.y, 2u * (unsigned)i1) EMIT(a1.w, 2u * (unsigned)i1 + 1u) }
        if (b2) { EMIT(a2.y, 2u * (unsigned)i2) EMIT(a2.w, 2u * (unsigned)i2 + 1u) }
        if (b3) { EMIT(a3.y, 2u * (unsigned)i3) EMIT(a3.w, 2u * (unsigned)i3 + 1u) }
        #undef EMIT
    }

    // ---- last-finishing block validates (exact fallback only if speculation failed)
    __shared__ int s_last;
    __syncthreads();
    if (threadIdx.x == 0) {
        __threadfence();
        unsigned d = atomicAdd(&g_done1, 1u);
        s_last = (d == gridDim.x - 1) ? 1 : 0;
    }
    __syncthreads();
    if (!s_last) return;

    int t = threadIdx.x;
    __shared__ int s_fb;
    if (t == 0) {
        g_done1 = 0;
        int c = g_candCount;
        s_fb = (c < MM || c > CAND);
        if (!s_fb) { g_cnt = c; g_nValid = MM; g_edgeCount = 0; }
    }
    __syncthreads();
    if (!s_fb) return;

    // pathological fallback: exact histogram selection by this one block
    __shared__ unsigned sh[NB];
    __shared__ unsigned s_cut;
    __shared__ int s_cnt2;
    for (int i = t; i < NB; i += 1024) sh[i] = 0u;
    __syncthreads();
    for (int i = t; i < n; i += 1024) {
        float v = score[i].y;
        if (v > 0.5f) {
            unsigned u = __float_as_uint(v);
            unsigned b = (u - 0x3F000000u) >> 11;
            if (b > NB - 1u) b = NB - 1u;
            atomicAdd(&sh[b], 1u);
        }
    }
    __syncthreads();
    if (t == 0) {
        unsigned run = 0; unsigned cut = 0;
        for (int b = NB - 1; b >= 0; b--) {
            run += sh[b];
            if (run >= (unsigned)MM) { cut = (unsigned)b; break; }
        }
        s_cut = cut;
        s_cnt2 = 0;
    }
    __syncthreads();
    unsigned cut = s_cut;
    for (int i = t; i < n; i += 1024) {
        float v = score[i].y;
        if (v > 0.5f) {
            unsigned u = __float_as_uint(v);
            unsigned b = (u - 0x3F000000u) >> 11;
            if (b > NB - 1u) b = NB - 1u;
            if (b >= cut) {
                int pos = atomicAdd(&s_cnt2, 1);
                if (pos < CAND)
                    g_cand[pos] = ((unsigned long long)u << 32) |
                                  (unsigned long long)(0xFFFFFFFFu - (unsigned)i);
            }
        }
    }
    __syncthreads();
    if (t == 0) {
        int c2 = s_cnt2; if (c2 > CAND) c2 = CAND;
        g_cnt = c2;
        g_nValid = (c2 < MM) ? c2 : MM;
        g_edgeCount = 0;
    }
}

// ---------------- grid barrier (all GRID blocks resident by construction) --------
__device__ __forceinline__ void grid_barrier() {
    __syncthreads();
    if (threadIdx.x == 0) {
        __threadfence();
        unsigned gen = g_gen;
        if (atomicAdd(&g_arrive, 1u) == (unsigned)gridDim.x - 1u) {
            atomicExch(&g_arrive, 0u);
            __threadfence();
            g_gen = gen + 1u;
        } else {
            while (g_gen == gen) __nanosleep(64);
        }
        __threadfence();
    }
    __syncthreads();
}

// ---------------- k_post: sliced rank+decode | barrier | pairs | finalize --------
__global__ void __launch_bounds__(1024, 2) k_post(const float4* __restrict__ anchors,
                                                  const float4* __restrict__ deltas,
                                                  float* __restrict__ out) {
    __shared__ union {
        unsigned long long keys[CAND];                                  // 32 KB (rank)
        struct { unsigned se[EDGE_MAX]; unsigned se2[EDGE_MAX];
                 unsigned char dead[MM]; } fin;                         // 34.4 KB
    } sh;
    __shared__ int s_rank[32];
    __shared__ float4 bjs[TB];
    __shared__ float  ajs[TB];
    __shared__ int    kjs[TB];
    int t = threadIdx.x;
    int cnt = g_cnt;
    int nV  = g_nValid;

    // ========== Phase A: sliced rank — every block ranks cpb candidates ==========
    {
        int cpb = (cnt + (int)gridDim.x - 1) / (int)gridDim.x;   // candidates/block (<=14 for cnt<=4096)
        int cBase = blockIdx.x * cpb;
        if (cpb > 0 && cBase < cnt) {
            int wpc = 32 / cpb;                                  // warps per candidate (>=2)
            int cntR = (cnt + 127) & ~127;
            for (int i = t; i < cntR; i += 1024) sh.keys[i] = (i < cnt) ? g_cand[i] : 0ULL;
            if (t < 32) s_rank[t] = 0;
            __syncthreads();
            int wid = t >> 5, lane = t & 31;
            int c = wid / wpc;
            int s = wid - c * wpc;
            int gc = cBase + c;
            if (c < cpb && gc < cnt) {
                unsigned long long my = sh.keys[gc];
                int sliceLen = (((cntR + wpc - 1) / wpc) + 127) & ~127;
                int b0 = s * sliceLen;
                int b1 = min(b0 + sliceLen, cntR);
                int g = 0;
                for (int base = b0; base < b1; base += 64) {
                    unsigned long long k0 = sh.keys[base      + lane];
                    unsigned long long k1 = sh.keys[base + 32 + lane];
                    g += __popc(__ballot_sync(0xffffffffu, k0 > my));
                    g += __popc(__ballot_sync(0xffffffffu, k1 > my));
                }
                if (lane == 0 && g) atomicAdd(&s_rank[c], g);
            }
            __syncthreads();
            // decode: one thread per candidate
            if (t < cpb && cBase + t < cnt) {
                int g = s_rank[t];
                if (g < MM) {
                    unsigned long long my = sh.keys[cBase + t];
                    unsigned idx = 0xFFFFFFFFu - (unsigned)(my & 0xFFFFFFFFull);
                    float4 a = __ldg(anchors + idx);
                    float4 d = __ldg(deltas + idx);
                    float w  = a.z - a.x;
                    float h  = a.w - a.y;
                    float cx = a.x + 0.5f * w;
                    float cy = a.y + 0.5f * h;
                    float ncx = cx + d.x * w;
                    float ncy = cy + d.y * h;
                    float nw  = w * expf(d.z);
                    float nh  = h * expf(d.w);
                    float x1 = ncx - 0.5f * nw, y1 = ncy - 0.5f * nh;
                    float x2 = ncx + 0.5f * nw, y2 = ncy + 0.5f * nh;
                    x1 = fminf(fmaxf(x1, 0.f), 1024.f);
                    y1 = fminf(fmaxf(y1, 0.f), 1024.f);
                    x2 = fminf(fmaxf(x2, 0.f), 1024.f);
                    y2 = fminf(fmaxf(y2, 0.f), 1024.f);
                    bool big = ((x2 - x1) >= 1.0f) && ((y2 - y1) >= 1.0f);
                    g_boxes[g] = make_float4(x1, y1, x2, y2);
                    g_keep0[g] = big ? 1 : 0;
                }
            }
        }
    }

    grid_barrier();   // all boxes/keep0 visible chip-wide

    // ========== Phase B: pairs — 64x64 tiles strided over the grid ==========
    for (int tile = blockIdx.x; tile < NTILES; tile += gridDim.x) {
        int bx = 0, rem = tile;
        while (rem >= NT - bx) { rem -= NT - bx; bx++; }
        int by = bx + rem;

        __syncthreads();
        if (t < TB) {
            int j = by * TB + t;
            if (j < nV) {
                float4 b = g_boxes[j];
                bjs[t] = b; ajs[t] = (b.z - b.x) * (b.w - b.y); kjs[t] = g_keep0[j];
            } else kjs[t] = 0;
        }
        __syncthreads();

        int li = t >> 4;
        int i  = bx * TB + li;
        if (i < nV && g_keep0[i]) {
            float4 A = g_boxes[i];
            float ai = (A.z - A.x) * (A.w - A.y);
            int ljBase = (t & 15) * 4;
            int jBase  = by * TB + ljBase;
            #pragma unroll
            for (int u = 0; u < 4; u++) {
                int lj = ljBase + u;
                int j  = jBase + u;
                if (j > i && j < nV && kjs[lj]) {
                    float4 B = bjs[lj];
                    float ltx = fmaxf(A.x, B.x), lty = fmaxf(A.y, B.y);
                    float rbx = fminf(A.z, B.z), rby = fminf(A.w, B.w);
                    float iw = fmaxf(rbx - ltx, 0.f), ih = fmaxf(rby - lty, 0.f);
                    float inter = iw * ih;
                    float iou = inter / (ai + ajs[lj] - inter + 1e-9f);
                    if (iou > 0.7f) {
                        int pos = atomicAdd(&g_edgeCount, 1);
                        if (pos < EDGE_MAX) g_edges[pos] = ((unsigned)i << 16) | (unsigned)j;
                    }
                }
            }
        }
    }

    // ========== last-finishing block: finalize ==========
    __shared__ int s_last;
    __syncthreads();
    if (t == 0) {
        __threadfence();
        unsigned d = atomicAdd(&g_done2, 1u);
        s_last = (d == gridDim.x - 1) ? 1 : 0;
    }
    __syncthreads();
    if (!s_last) return;

    for (int m = t; m < MM; m += 1024) sh.fin.dead[m] = (m < nV && g_keep0[m]) ? 0 : 1;
    int ec = g_edgeCount; if (ec > EDGE_MAX) ec = EDGE_MAX;
    for (int i = t; i < ec; i += 1024) sh.fin.se[i] = g_edges[i];
    __syncthreads();

    // parallel counting-rank sort: distinct (i<<16|j) keys
    for (int e = t; e < ec; e += 1024) {
        unsigned key = sh.fin.se[e];
        int r = 0;
        for (int f = 0; f < ec; f++) r += (sh.fin.se[f] < key) ? 1 : 0;
        sh.fin.se2[r] = key;
    }
    __syncthreads();

    if (t == 0) {
        for (int e = 0; e < ec; e++) {
            unsigned u = sh.fin.se2[e];
            int i = (int)(u >> 16), j = (int)(u & 0xFFFFu);
            if (!sh.fin.dead[i]) sh.fin.dead[j] = 1;
        }
    }
    __syncthreads();

    for (int m = t; m < MM; m += 1024) {
        bool keep = (sh.fin.dead[m] == 0);
        float4 b = g_boxes[m];
        out[m * 4 + 0] = keep ? b.x : 0.f;
        out[m * 4 + 1] = keep ? b.y : 0.f;
        out[m * 4 + 2] = keep ? b.z : 0.f;
        out[m * 4 + 3] = keep ? b.w : 0.f;
        out[MM * 4 + m] = keep ? 1.f : 0.f;
    }
    __syncthreads();
    if (t == 0) {   // reset for next replay
        g_candCount = 0;
        g_edgeCount = 0;
        g_done2 = 0;
    }
}

// ---------------- launch ----------------
extern "C" void kernel_launch(void* const* d_in, const int* in_sizes, int n_in,
                              void* d_out, int out_size) {
    int si = 0;
    for (int i = 1; i < n_in; i++) if (in_sizes[i] < in_sizes[si]) si = i;
    int others[2], o = 0;
    for (int i = 0; i < n_in && o < 2; i++) if (i != si) others[o++] = i;

    const float4* anchors = (const float4*)d_in[others[0]];
    const float2* score   = (const float2*)d_in[si];
    const float4* deltas  = (const float4*)d_in[others[1]];
    int n  = in_sizes[si] / 2;
    int n4 = in_sizes[si] / 4;

    k_main<<<296, 1024>>>((const float4*)score, n4, score, n);
    k_post<<<GRID, 1024>>>(anchors, deltas, (float*)d_out);
}